// round 16
// baseline (speedup 1.0000x reference)
#include <cuda_runtime.h>
#include <cuda_fp16.h>
#include <cstdint>
#include <math.h>

#define BB 4
#define NN 8192
#define SS 512
#define CCH 1536
#define MCH 512
#define RR (BB*NN)   // 32768 rows
#define SR (BB*SS)   // 2048 center rows

// ---------------- scratch (static device globals; no allocation) ----------------
static __device__ __half g_F[(size_t)SR * CCH];            // 6 MB fused centers fp16
static __device__ __half g_W1[MCH * CCH];
static __device__ __half g_W2[MCH * MCH];
static __device__ __half g_Yh[(size_t)SR * MCH];           // 2 MB Y fp16
static __device__ __half g_A2[(size_t)RR * MCH];           // 33 MB relu(bn1(x1)) fp16
static __device__ __half g_x1[(size_t)RR * MCH];           // 33 MB (pre-BN, fp16)
static __device__ __half g_x2[(size_t)RR * MCH];           // 33 MB (pre-BN, fp16)
static __device__ int   g_kidx[RR * 3];
static __device__ float g_kw[RR * 3];
static __device__ float g_stats[4 * MCH];                  // sum1, sq1, sum2, sq2
static __device__ float g_affine[4 * MCH];                 // scale1, shift1, scale2, shift2

// ---------------- helpers ----------------
__device__ __forceinline__ uint32_t smem_u32(const void* p) {
    uint32_t a;
    asm("{ .reg .u64 t; cvta.to.shared.u64 t, %1; cvt.u32.u64 %0, t; }" : "=r"(a) : "l"(p));
    return a;
}
__device__ __forceinline__ void cp16(uint32_t saddr, const void* g) {
    asm volatile("cp.async.cg.shared.global [%0], [%1], 16;" :: "r"(saddr), "l"(g) : "memory");
}

#define LDSM4(R0, R1, R2, R3, ADDR) \
    asm volatile("ldmatrix.sync.aligned.m8n8.x4.shared.b16 {%0,%1,%2,%3}, [%4];" \
                 : "=r"(R0), "=r"(R1), "=r"(R2), "=r"(R3) : "r"(ADDR))

#define MMA16816(c, a, b) \
    asm volatile("mma.sync.aligned.m16n8k16.row.col.f32.f16.f16.f32 " \
                 "{%0,%1,%2,%3},{%4,%5,%6,%7},{%8,%9},{%0,%1,%2,%3};" \
                 : "+f"((c)[0]), "+f"((c)[1]), "+f"((c)[2]), "+f"((c)[3]) \
                 : "r"((a)[0]), "r"((a)[1]), "r"((a)[2]), "r"((a)[3]), \
                   "r"((b)[0]), "r"((b)[1]))

// ---------------- prep: W1/W2 -> fp16, F build, stats zero (one kernel) ----------------
#define W1N (MCH * CCH)              // 786432
#define W2N (MCH * MCH)              // 262144
#define FN  (SR * CCH)               // 3145728
__global__ void prep_kernel(const float* __restrict__ W1,
                            const float* __restrict__ W2,
                            const float* __restrict__ H4,
                            const float* __restrict__ H8,
                            const float* __restrict__ H12) {
    int i = blockIdx.x * blockDim.x + threadIdx.x;    // 0 .. 4194303
    if (i < 4 * MCH) g_stats[i] = 0.0f;
    if (i < W1N) {
        g_W1[i] = __float2half(W1[i]);
    } else if (i < W1N + W2N) {
        int j = i - W1N;
        g_W2[j] = __float2half(W2[j]);
    } else {
        int f = i - (W1N + W2N);                      // 0 .. FN-1
        int r = f / CCH;
        int c = f - r * CCH;
        int b = r >> 9, s = r & 511;
        int sec = c >> 9, off = c & 511;
        const float* src = (sec == 0) ? H4 : ((sec == 1) ? H8 : H12);
        g_F[(size_t)r * CCH + c] = __float2half(src[((size_t)(b * SS + s)) * 512 + off]);
    }
}

// ---------------- KNN (top-3 smallest squared distances) ----------------
__global__ void knn_kernel(const float* __restrict__ xyz,
                           const float* __restrict__ centers) {
    __shared__ float sc[SS * 3];
    __shared__ float scn[SS];
    int p = blockIdx.x * blockDim.x + threadIdx.x;
    int b = p >> 13;
    for (int i = threadIdx.x; i < SS * 3; i += blockDim.x)
        sc[i] = centers[b * SS * 3 + i];
    __syncthreads();
    for (int s = threadIdx.x; s < SS; s += blockDim.x) {
        float c0 = sc[s*3], c1 = sc[s*3+1], c2 = sc[s*3+2];
        scn[s] = c0*c0 + c1*c1 + c2*c2;
    }
    __syncthreads();

    float x0 = xyz[p*3+0], x1 = xyz[p*3+1], x2 = xyz[p*3+2];
    float xx = x0*x0 + x1*x1 + x2*x2;

    float bd0 = 3.4e38f, bd1 = 3.4e38f, bd2 = 3.4e38f;
    int   bi0 = 0, bi1 = 0, bi2 = 0;
    for (int s = 0; s < SS; s++) {
        float c0 = sc[s*3], c1 = sc[s*3+1], c2 = sc[s*3+2];
        float dot = x0*c0 + x1*c1 + x2*c2;
        float d = xx - 2.0f * dot + scn[s];
        if (d < bd2) {
            if (d < bd1) {
                bd2 = bd1; bi2 = bi1;
                if (d < bd0) { bd1 = bd0; bi1 = bi0; bd0 = d; bi0 = s; }
                else         { bd1 = d;  bi1 = s; }
            } else { bd2 = d; bi2 = s; }
        }
    }
    float r0 = 1.0f / (bd0 + 1e-8f);
    float r1 = 1.0f / (bd1 + 1e-8f);
    float r2 = 1.0f / (bd2 + 1e-8f);
    float inv = 1.0f / (r0 + r1 + r2);
    g_kidx[p*3+0] = bi0; g_kidx[p*3+1] = bi1; g_kidx[p*3+2] = bi2;
    g_kw[p*3+0] = r0 * inv; g_kw[p*3+1] = r1 * inv; g_kw[p*3+2] = r2 * inv;
}

// ---------------- fp16 HMMA GEMM (plain mainloop) ----------------
// Warp grid 2(M)x4(N); warp tile (MF*16)x32; CTA tile (MF*32)x128.
// K-chunk 32, cp.async double buffer, ldmatrix frags, m16n8k16 fp32 accum.
// LAYER 0 (MF=2): Y-GEMM. A=g_F, K=1536, out=g_Yh fp16, no bias/stats. 128 CTAs = 1 wave.
// LAYER 1 (MF=4): layer2. A=g_A2, out=g_x2 fp16 + bias + fused fp32 stats.
#define ROWSTRIDE 80

template<int MF, int KSTRIDE, int LAYER>
__global__ void __launch_bounds__(256, 2)
hmma_gemm_kernel(const float* __restrict__ bias) {
    extern __shared__ __align__(128) char smem[];
    const __half* A = LAYER ? g_A2 : g_F;
    const __half* W = LAYER ? g_W2 : g_W1;

    constexpr int AROWS = MF * 32;                    // 64 or 128
    constexpr int AOFF  = AROWS * ROWSTRIDE;          // W base within stage
    constexpr int STGB  = (AROWS + 128) * ROWSTRIDE;  // stage bytes
    constexpr int NCH   = KSTRIDE / 32;

    const int tid  = threadIdx.x;
    const int wid  = tid >> 5;
    const int lane = tid & 31;
    const int wm   = wid >> 2;        // 0..1
    const int wn   = wid & 3;         // 0..3
    const int brow = blockIdx.y * AROWS;
    const int bcol = blockIdx.x * 128;

    const uint32_t sbase = smem_u32(smem);

    // ldmatrix per-lane address components
    const int arow  = (lane & 7) + ((lane >> 3) & 1) * 8;
    const int akoff = (lane >> 4) * 16;
    const int brw   = (lane & 7) + ((lane >> 4) & 1) * 8;
    const int bkoff = ((lane >> 3) & 1) * 16;

    const uint32_t aBase = sbase + (wm * (MF * 16) + arow) * ROWSTRIDE + akoff;
    const uint32_t bBase = sbase + AOFF + (wn * 32 + brw) * ROWSTRIDE + bkoff;

    float acc[MF][4][4];
#pragma unroll
    for (int mf = 0; mf < MF; mf++)
#pragma unroll
        for (int nf = 0; nf < 4; nf++)
#pragma unroll
            for (int q = 0; q < 4; q++) acc[mf][nf][q] = 0.f;

    auto issue = [&](int chunk, int stage) {
        const uint32_t sb = sbase + stage * STGB;
        const int kc = chunk * 32;
#pragma unroll
        for (int j = 0; j < (AROWS * 4) / 256; j++) {
            int lin = tid + j * 256;
            int row = lin >> 2;
            int seg = lin & 3;
            cp16(sb + row * ROWSTRIDE + seg * 16,
                 A + (size_t)(brow + row) * KSTRIDE + kc + seg * 8);
        }
#pragma unroll
        for (int j = 0; j < 2; j++) {
            int lin = tid + j * 256;
            int row = lin >> 2;
            int seg = lin & 3;
            cp16(sb + AOFF + row * ROWSTRIDE + seg * 16,
                 W + (size_t)(bcol + row) * KSTRIDE + kc + seg * 8);
        }
        asm volatile("cp.async.commit_group;" ::: "memory");
    };

    issue(0, 0);

    for (int c = 0; c < NCH; c++) {
        if (c + 1 < NCH) {
            issue(c + 1, (c + 1) & 1);
            asm volatile("cp.async.wait_group 1;" ::: "memory");
        } else {
            asm volatile("cp.async.wait_group 0;" ::: "memory");
        }
        __syncthreads();

        const uint32_t stg = (c & 1) * STGB;

#pragma unroll
        for (int kk = 0; kk < 2; kk++) {
            const int kb = kk * 32;   // bytes into 64B row
            uint32_t a[MF][4], bb[4][2];
#pragma unroll
            for (int mf = 0; mf < MF; mf++)
                LDSM4(a[mf][0], a[mf][1], a[mf][2], a[mf][3],
                      aBase + stg + mf * (16 * ROWSTRIDE) + kb);
#pragma unroll
            for (int np = 0; np < 2; np++)
                LDSM4(bb[np*2][0], bb[np*2][1], bb[np*2+1][0], bb[np*2+1][1],
                      bBase + stg + np * (16 * ROWSTRIDE) + kb);
#pragma unroll
            for (int mf = 0; mf < MF; mf++)
#pragma unroll
                for (int nf = 0; nf < 4; nf++)
                    MMA16816(acc[mf][nf], a[mf], bb[nf]);
        }
        __syncthreads();
    }

    const int r0 = brow + wm * (MF * 16) + (lane >> 2);
    const int cc = bcol + wn * 32 + (lane & 3) * 2;

    if (LAYER == 0) {
#pragma unroll
        for (int nf = 0; nf < 4; nf++) {
            int col = cc + nf * 8;
#pragma unroll
            for (int mf = 0; mf < MF; mf++) {
#pragma unroll
                for (int rr = 0; rr < 2; rr++) {
                    int row = r0 + mf * 16 + rr * 8;
                    *(__half2*)&g_Yh[(size_t)row * MCH + col] =
                        __floats2half2_rn(acc[mf][nf][rr * 2 + 0], acc[mf][nf][rr * 2 + 1]);
                }
            }
        }
    } else {
        __half* out = g_x2;
        float* statSum = g_stats + 2 * MCH;
        float* statSq  = statSum + MCH;
        float s[8], q[8];
#pragma unroll
        for (int i = 0; i < 8; i++) { s[i] = 0.f; q[i] = 0.f; }

#pragma unroll
        for (int nf = 0; nf < 4; nf++) {
            int col = cc + nf * 8;
            float b0 = bias[col], b1 = bias[col + 1];
#pragma unroll
            for (int mf = 0; mf < MF; mf++) {
#pragma unroll
                for (int rr = 0; rr < 2; rr++) {
                    int row = r0 + mf * 16 + rr * 8;
                    float v0 = acc[mf][nf][rr * 2 + 0] + b0;
                    float v1 = acc[mf][nf][rr * 2 + 1] + b1;
                    *(__half2*)&out[(size_t)row * MCH + col] = __floats2half2_rn(v0, v1);
                    s[nf*2]   += v0; q[nf*2]   += v0 * v0;
                    s[nf*2+1] += v1; q[nf*2+1] += v1 * v1;
                }
            }
        }
#pragma unroll
        for (int off = 16; off >= 4; off >>= 1) {
#pragma unroll
            for (int i = 0; i < 8; i++) {
                s[i] += __shfl_down_sync(0xffffffffu, s[i], off);
                q[i] += __shfl_down_sync(0xffffffffu, q[i], off);
            }
        }
        if ((lane >> 2) == 0) {
#pragma unroll
            for (int nf = 0; nf < 4; nf++) {
#pragma unroll
                for (int cbit = 0; cbit < 2; cbit++) {
                    int col = cc + nf * 8 + cbit;
                    atomicAdd(&statSum[col], s[nf*2 + cbit]);
                    atomicAdd(&statSq[col],  q[nf*2 + cbit]);
                }
            }
        }
    }
}

// ---------------- gather: x1[p] = sum_k w_k * Yh[idx_k] + b1, fp16 out + stats ----------------
// R9 loop shape and launch bounds; GPTS=32 doubles grid to 1024 CTAs to lift the
// grid-limited occupancy (regs stay unclamped at bounds(256,4)).
#define GPTS 32
__global__ void __launch_bounds__(256, 4)
gather_kernel(const float* __restrict__ b1) {
    __shared__ int   si[GPTS][3];
    __shared__ float sw_[GPTS][3];
    int p0 = blockIdx.x * GPTS;
    int t = threadIdx.x;
    if (t < GPTS * 3) {
        int j = t / 3, k = t - j * 3;
        int p = p0 + j;
        si[j][k]  = (p >> 13) * SS + g_kidx[p * 3 + k];   // global Y row
        sw_[j][k] = g_kw[p * 3 + k];
    }
    __syncthreads();

    int c0 = t * 2;                    // 0..510
    float bb0 = b1[c0], bb1 = b1[c0 + 1];
    float s0 = 0.f, s1 = 0.f, q0 = 0.f, q1 = 0.f;

#pragma unroll 4
    for (int j = 0; j < GPTS; j++) {
        float v0 = bb0, v1 = bb1;
#pragma unroll
        for (int k = 0; k < 3; k++) {
            __half2 y = *(const __half2*)(g_Yh + (size_t)si[j][k] * MCH + c0);
            float2 yf = __half22float2(y);
            float w = sw_[j][k];
            v0 += w * yf.x; v1 += w * yf.y;
        }
        *(__half2*)&g_x1[(size_t)(p0 + j) * MCH + c0] = __floats2half2_rn(v0, v1);
        s0 += v0; q0 += v0 * v0;
        s1 += v1; q1 += v1 * v1;
    }
    atomicAdd(&g_stats[c0],           s0);
    atomicAdd(&g_stats[c0 + 1],       s1);
    atomicAdd(&g_stats[MCH + c0],     q0);
    atomicAdd(&g_stats[MCH + c0 + 1], q1);
}

// ---------------- BN finalize ----------------
__global__ void finalize_kernel(const float* __restrict__ gamma,
                                const float* __restrict__ beta, int layer) {
    int c = threadIdx.x;   // 512 threads
    float mean = g_stats[layer * 2 * MCH + c] * (1.0f / RR);
    float var  = g_stats[layer * 2 * MCH + MCH + c] * (1.0f / RR) - mean * mean;
    float rstd = rsqrtf(var + 1e-5f);
    float sc = gamma[c] * rstd;
    g_affine[layer * 2 * MCH + c]       = sc;
    g_affine[layer * 2 * MCH + MCH + c] = beta[c] - mean * sc;
}

// ---------------- layer2 input map: relu(bn1(x1)) -> fp16 A2 ----------------
__global__ void map2_kernel() {
    int i = blockIdx.x * blockDim.x + threadIdx.x;   // 4-col group index over RR*128
    int c4 = i & 127;
    uint2 raw = ((const uint2*)g_x1)[i];
    __half2 h01 = *(__half2*)&raw.x;
    __half2 h23 = *(__half2*)&raw.y;
    float4 s = ((const float4*)g_affine)[c4];
    float4 t = ((const float4*)(g_affine + MCH))[c4];
    float v0 = fmaxf(fmaf(__low2float(h01),  s.x, t.x), 0.f);
    float v1 = fmaxf(fmaf(__high2float(h01), s.y, t.y), 0.f);
    float v2 = fmaxf(fmaf(__low2float(h23),  s.z, t.z), 0.f);
    float v3 = fmaxf(fmaf(__high2float(h23), s.w, t.w), 0.f);
    uint2 o;
    *(__half2*)&o.x = __floats2half2_rn(v0, v1);
    *(__half2*)&o.y = __floats2half2_rn(v2, v3);
    ((uint2*)g_A2)[i] = o;
}

// ---------------- final map: out = relu(x2 * scale2 + shift2) ----------------
__global__ void finalmap_kernel(float* __restrict__ out) {
    int i = blockIdx.x * blockDim.x + threadIdx.x;
    int c4 = i & 127;
    uint2 raw = ((const uint2*)g_x2)[i];
    __half2 h01 = *(__half2*)&raw.x;
    __half2 h23 = *(__half2*)&raw.y;
    float4 s = ((const float4*)(g_affine + 2 * MCH))[c4];
    float4 t = ((const float4*)(g_affine + 3 * MCH))[c4];
    float4 v;
    v.x = fmaxf(fmaf(__low2float(h01),  s.x, t.x), 0.f);
    v.y = fmaxf(fmaf(__high2float(h01), s.y, t.y), 0.f);
    v.z = fmaxf(fmaf(__low2float(h23),  s.z, t.z), 0.f);
    v.w = fmaxf(fmaf(__high2float(h23), s.w, t.w), 0.f);
    ((float4*)out)[i] = v;
}

// ---------------- launch ----------------
extern "C" void kernel_launch(void* const* d_in, const int* in_sizes, int n_in,
                              void* d_out, int out_size) {
    const float* xyz     = (const float*)d_in[0];
    const float* centers = (const float*)d_in[1];
    const float* H4      = (const float*)d_in[2];
    const float* H8      = (const float*)d_in[3];
    const float* H12     = (const float*)d_in[4];
    const float* W1      = (const float*)d_in[5];
    const float* b1      = (const float*)d_in[6];
    const float* g1      = (const float*)d_in[7];
    const float* beta1   = (const float*)d_in[8];
    const float* W2      = (const float*)d_in[9];
    const float* b2      = (const float*)d_in[10];
    const float* g2      = (const float*)d_in[11];
    const float* beta2   = (const float*)d_in[12];
    float* out = (float*)d_out;

    const int SMEM_Y  = 2 * (64 + 128) * ROWSTRIDE;    // 30720
    const int SMEM_G2 = 2 * (128 + 128) * ROWSTRIDE;   // 40960
    cudaFuncSetAttribute(hmma_gemm_kernel<2, CCH, 0>,
                         cudaFuncAttributeMaxDynamicSharedMemorySize, SMEM_Y);
    cudaFuncSetAttribute(hmma_gemm_kernel<4, MCH, 1>,
                         cudaFuncAttributeMaxDynamicSharedMemorySize, SMEM_G2);

    prep_kernel<<<(W1N + W2N + FN) / 256, 256>>>(W1, W2, H4, H8, H12);
    knn_kernel<<<RR / 256, 256>>>(xyz, centers);

    // Y = F @ W1 (2048 x 512, K=1536) — single wave (128 CTAs), fp16 out
    dim3 gy(MCH / 128, SR / 64);       // (4, 32)
    hmma_gemm_kernel<2, CCH, 0><<<gy, 256, SMEM_Y>>>(nullptr);

    // x1 = interp(Yh) + b1  (+ stats)
    gather_kernel<<<RR / GPTS, 256>>>(b1);

    finalize_kernel<<<1, 512>>>(g1, beta1, 0);
    map2_kernel<<<(RR * 128) / 256, 256>>>();

    // x2 = A2 @ W2 + b2  (+ stats)
    dim3 g2d(MCH / 128, RR / 128);     // (4, 256)
    hmma_gemm_kernel<4, MCH, 1><<<g2d, 256, SMEM_G2>>>(b2);

    finalize_kernel<<<1, 512>>>(g2, beta2, 1);

    finalmap_kernel<<<(RR * 128) / 256, 256>>>(out);
}

// round 17
// speedup vs baseline: 1.0835x; 1.0835x over previous
#include <cuda_runtime.h>
#include <cuda_fp16.h>
#include <cstdint>
#include <math.h>

#define BB 4
#define NN 8192
#define SS 512
#define CCH 1536
#define MCH 512
#define RR (BB*NN)   // 32768 rows
#define SR (BB*SS)   // 2048 center rows

// ---------------- scratch (static device globals; no allocation) ----------------
static __device__ __half g_F[(size_t)SR * CCH];            // 6 MB fused centers fp16
static __device__ __half g_W1[MCH * CCH];
static __device__ __half g_W2[MCH * MCH];
static __device__ __half g_Yh[(size_t)SR * MCH];           // 2 MB Y fp16
static __device__ __half g_A2[(size_t)RR * MCH];           // 33 MB relu(bn1(x1)) fp16
static __device__ __half g_x1[(size_t)RR * MCH];           // 33 MB (pre-BN, fp16)
static __device__ __half g_x2[(size_t)RR * MCH];           // 33 MB (pre-BN, fp16)
static __device__ int   g_kidx[RR * 3];
static __device__ float g_kw[RR * 3];
static __device__ float g_stats[4 * MCH];                  // sum1, sq1, sum2, sq2

// ---------------- helpers ----------------
__device__ __forceinline__ uint32_t smem_u32(const void* p) {
    uint32_t a;
    asm("{ .reg .u64 t; cvta.to.shared.u64 t, %1; cvt.u32.u64 %0, t; }" : "=r"(a) : "l"(p));
    return a;
}
__device__ __forceinline__ void cp16(uint32_t saddr, const void* g) {
    asm volatile("cp.async.cg.shared.global [%0], [%1], 16;" :: "r"(saddr), "l"(g) : "memory");
}

#define LDSM4(R0, R1, R2, R3, ADDR) \
    asm volatile("ldmatrix.sync.aligned.m8n8.x4.shared.b16 {%0,%1,%2,%3}, [%4];" \
                 : "=r"(R0), "=r"(R1), "=r"(R2), "=r"(R3) : "r"(ADDR))

#define MMA16816(c, a, b) \
    asm volatile("mma.sync.aligned.m16n8k16.row.col.f32.f16.f16.f32 " \
                 "{%0,%1,%2,%3},{%4,%5,%6,%7},{%8,%9},{%0,%1,%2,%3};" \
                 : "+f"((c)[0]), "+f"((c)[1]), "+f"((c)[2]), "+f"((c)[3]) \
                 : "r"((a)[0]), "r"((a)[1]), "r"((a)[2]), "r"((a)[3]), \
                   "r"((b)[0]), "r"((b)[1]))

// ---------------- prep: W1/W2 -> fp16, F build, stats zero (x4 widened) ----------------
#define W1N (MCH * CCH)              // 786432
#define W2N (MCH * MCH)              // 262144
#define FN  (SR * CCH)               // 3145728
__global__ void prep_kernel(const float* __restrict__ W1,
                            const float* __restrict__ W2,
                            const float* __restrict__ H4,
                            const float* __restrict__ H8,
                            const float* __restrict__ H12) {
    int g = blockIdx.x * blockDim.x + threadIdx.x;    // 4-elem group, 0..1048575
    int i = g * 4;
    if (i < 4 * MCH) {
        float4 z = make_float4(0.f, 0.f, 0.f, 0.f);
        *(float4*)&g_stats[i] = z;
    }
    const float* src;
    __half* dst;
    int off;
    if (i < W1N) {
        src = W1 + i; dst = g_W1 + i; off = 0;
        float4 v = *(const float4*)src;
        __half h[4] = {__float2half(v.x), __float2half(v.y), __float2half(v.z), __float2half(v.w)};
        *(uint2*)dst = *(uint2*)h;
    } else if (i < W1N + W2N) {
        int j = i - W1N;
        float4 v = *(const float4*)(W2 + j);
        __half h[4] = {__float2half(v.x), __float2half(v.y), __float2half(v.z), __float2half(v.w)};
        *(uint2*)(g_W2 + j) = *(uint2*)h;
    } else {
        int f = i - (W1N + W2N);                      // 0 .. FN-1, 4-aligned
        int r = f / CCH;
        int c = f - r * CCH;                          // 4-aligned, section-safe (512%4==0)
        int b = r >> 9, s = r & 511;
        int sec = c >> 9; off = c & 511;
        src = (sec == 0) ? H4 : ((sec == 1) ? H8 : H12);
        float4 v = *(const float4*)(src + ((size_t)(b * SS + s)) * 512 + off);
        __half h[4] = {__float2half(v.x), __float2half(v.y), __float2half(v.z), __float2half(v.w)};
        *(uint2*)(g_F + (size_t)r * CCH + c) = *(uint2*)h;
    }
}

// ---------------- KNN (top-3 smallest squared distances) ----------------
__global__ void knn_kernel(const float* __restrict__ xyz,
                           const float* __restrict__ centers) {
    __shared__ float sc[SS * 3];
    __shared__ float scn[SS];
    int p = blockIdx.x * blockDim.x + threadIdx.x;
    int b = p >> 13;
    for (int i = threadIdx.x; i < SS * 3; i += blockDim.x)
        sc[i] = centers[b * SS * 3 + i];
    __syncthreads();
    for (int s = threadIdx.x; s < SS; s += blockDim.x) {
        float c0 = sc[s*3], c1 = sc[s*3+1], c2 = sc[s*3+2];
        scn[s] = c0*c0 + c1*c1 + c2*c2;
    }
    __syncthreads();

    float x0 = xyz[p*3+0], x1 = xyz[p*3+1], x2 = xyz[p*3+2];
    float xx = x0*x0 + x1*x1 + x2*x2;

    float bd0 = 3.4e38f, bd1 = 3.4e38f, bd2 = 3.4e38f;
    int   bi0 = 0, bi1 = 0, bi2 = 0;
    for (int s = 0; s < SS; s++) {
        float c0 = sc[s*3], c1 = sc[s*3+1], c2 = sc[s*3+2];
        float dot = x0*c0 + x1*c1 + x2*c2;
        float d = xx - 2.0f * dot + scn[s];
        if (d < bd2) {
            if (d < bd1) {
                bd2 = bd1; bi2 = bi1;
                if (d < bd0) { bd1 = bd0; bi1 = bi0; bd0 = d; bi0 = s; }
                else         { bd1 = d;  bi1 = s; }
            } else { bd2 = d; bi2 = s; }
        }
    }
    float r0 = 1.0f / (bd0 + 1e-8f);
    float r1 = 1.0f / (bd1 + 1e-8f);
    float r2 = 1.0f / (bd2 + 1e-8f);
    float inv = 1.0f / (r0 + r1 + r2);
    g_kidx[p*3+0] = bi0; g_kidx[p*3+1] = bi1; g_kidx[p*3+2] = bi2;
    g_kw[p*3+0] = r0 * inv; g_kw[p*3+1] = r1 * inv; g_kw[p*3+2] = r2 * inv;
}

// ---------------- fp16 HMMA GEMM (plain mainloop) ----------------
// Warp grid 2(M)x4(N); warp tile (MF*16)x32; CTA tile (MF*32)x128.
// K-chunk 32, cp.async double buffer, ldmatrix frags, m16n8k16 fp32 accum.
// LAYER 0 (MF=2): Y-GEMM. A=g_F, K=1536, out=g_Yh fp16, no bias/stats. 128 CTAs = 1 wave.
// LAYER 1 (MF=4): layer2. A=g_A2, out=g_x2 fp16 + bias + fused fp32 stats.
#define ROWSTRIDE 80

template<int MF, int KSTRIDE, int LAYER>
__global__ void __launch_bounds__(256, 2)
hmma_gemm_kernel(const float* __restrict__ bias) {
    extern __shared__ __align__(128) char smem[];
    const __half* A = LAYER ? g_A2 : g_F;
    const __half* W = LAYER ? g_W2 : g_W1;

    constexpr int AROWS = MF * 32;                    // 64 or 128
    constexpr int AOFF  = AROWS * ROWSTRIDE;          // W base within stage
    constexpr int STGB  = (AROWS + 128) * ROWSTRIDE;  // stage bytes
    constexpr int NCH   = KSTRIDE / 32;

    const int tid  = threadIdx.x;
    const int wid  = tid >> 5;
    const int lane = tid & 31;
    const int wm   = wid >> 2;        // 0..1
    const int wn   = wid & 3;         // 0..3
    const int brow = blockIdx.y * AROWS;
    const int bcol = blockIdx.x * 128;

    const uint32_t sbase = smem_u32(smem);

    // ldmatrix per-lane address components
    const int arow  = (lane & 7) + ((lane >> 3) & 1) * 8;
    const int akoff = (lane >> 4) * 16;
    const int brw   = (lane & 7) + ((lane >> 4) & 1) * 8;
    const int bkoff = ((lane >> 3) & 1) * 16;

    const uint32_t aBase = sbase + (wm * (MF * 16) + arow) * ROWSTRIDE + akoff;
    const uint32_t bBase = sbase + AOFF + (wn * 32 + brw) * ROWSTRIDE + bkoff;

    float acc[MF][4][4];
#pragma unroll
    for (int mf = 0; mf < MF; mf++)
#pragma unroll
        for (int nf = 0; nf < 4; nf++)
#pragma unroll
            for (int q = 0; q < 4; q++) acc[mf][nf][q] = 0.f;

    auto issue = [&](int chunk, int stage) {
        const uint32_t sb = sbase + stage * STGB;
        const int kc = chunk * 32;
#pragma unroll
        for (int j = 0; j < (AROWS * 4) / 256; j++) {
            int lin = tid + j * 256;
            int row = lin >> 2;
            int seg = lin & 3;
            cp16(sb + row * ROWSTRIDE + seg * 16,
                 A + (size_t)(brow + row) * KSTRIDE + kc + seg * 8);
        }
#pragma unroll
        for (int j = 0; j < 2; j++) {
            int lin = tid + j * 256;
            int row = lin >> 2;
            int seg = lin & 3;
            cp16(sb + AOFF + row * ROWSTRIDE + seg * 16,
                 W + (size_t)(bcol + row) * KSTRIDE + kc + seg * 8);
        }
        asm volatile("cp.async.commit_group;" ::: "memory");
    };

    issue(0, 0);

    for (int c = 0; c < NCH; c++) {
        if (c + 1 < NCH) {
            issue(c + 1, (c + 1) & 1);
            asm volatile("cp.async.wait_group 1;" ::: "memory");
        } else {
            asm volatile("cp.async.wait_group 0;" ::: "memory");
        }
        __syncthreads();

        const uint32_t stg = (c & 1) * STGB;

#pragma unroll
        for (int kk = 0; kk < 2; kk++) {
            const int kb = kk * 32;   // bytes into 64B row
            uint32_t a[MF][4], bb[4][2];
#pragma unroll
            for (int mf = 0; mf < MF; mf++)
                LDSM4(a[mf][0], a[mf][1], a[mf][2], a[mf][3],
                      aBase + stg + mf * (16 * ROWSTRIDE) + kb);
#pragma unroll
            for (int np = 0; np < 2; np++)
                LDSM4(bb[np*2][0], bb[np*2][1], bb[np*2+1][0], bb[np*2+1][1],
                      bBase + stg + np * (16 * ROWSTRIDE) + kb);
#pragma unroll
            for (int mf = 0; mf < MF; mf++)
#pragma unroll
                for (int nf = 0; nf < 4; nf++)
                    MMA16816(acc[mf][nf], a[mf], bb[nf]);
        }
        __syncthreads();
    }

    const int r0 = brow + wm * (MF * 16) + (lane >> 2);
    const int cc = bcol + wn * 32 + (lane & 3) * 2;

    if (LAYER == 0) {
#pragma unroll
        for (int nf = 0; nf < 4; nf++) {
            int col = cc + nf * 8;
#pragma unroll
            for (int mf = 0; mf < MF; mf++) {
#pragma unroll
                for (int rr = 0; rr < 2; rr++) {
                    int row = r0 + mf * 16 + rr * 8;
                    *(__half2*)&g_Yh[(size_t)row * MCH + col] =
                        __floats2half2_rn(acc[mf][nf][rr * 2 + 0], acc[mf][nf][rr * 2 + 1]);
                }
            }
        }
    } else {
        __half* out = g_x2;
        float* statSum = g_stats + 2 * MCH;
        float* statSq  = statSum + MCH;
        float s[8], q[8];
#pragma unroll
        for (int i = 0; i < 8; i++) { s[i] = 0.f; q[i] = 0.f; }

#pragma unroll
        for (int nf = 0; nf < 4; nf++) {
            int col = cc + nf * 8;
            float b0 = bias[col], b1 = bias[col + 1];
#pragma unroll
            for (int mf = 0; mf < MF; mf++) {
#pragma unroll
                for (int rr = 0; rr < 2; rr++) {
                    int row = r0 + mf * 16 + rr * 8;
                    float v0 = acc[mf][nf][rr * 2 + 0] + b0;
                    float v1 = acc[mf][nf][rr * 2 + 1] + b1;
                    *(__half2*)&out[(size_t)row * MCH + col] = __floats2half2_rn(v0, v1);
                    s[nf*2]   += v0; q[nf*2]   += v0 * v0;
                    s[nf*2+1] += v1; q[nf*2+1] += v1 * v1;
                }
            }
        }
#pragma unroll
        for (int off = 16; off >= 4; off >>= 1) {
#pragma unroll
            for (int i = 0; i < 8; i++) {
                s[i] += __shfl_down_sync(0xffffffffu, s[i], off);
                q[i] += __shfl_down_sync(0xffffffffu, q[i], off);
            }
        }
        if ((lane >> 2) == 0) {
#pragma unroll
            for (int nf = 0; nf < 4; nf++) {
#pragma unroll
                for (int cbit = 0; cbit < 2; cbit++) {
                    int col = cc + nf * 8 + cbit;
                    atomicAdd(&statSum[col], s[nf*2 + cbit]);
                    atomicAdd(&statSq[col],  q[nf*2 + cbit]);
                }
            }
        }
    }
}

// ---------------- gather: x1[p] = sum_k w_k * Yh[idx_k] + b1, fp16 out + stats ----------------
// R9-proven shape (GPTS=64, bounds(256,4), per-thread 2 cols, direct atomics). DO NOT TOUCH.
#define GPTS 64
__global__ void __launch_bounds__(256, 4)
gather_kernel(const float* __restrict__ b1) {
    __shared__ int   si[GPTS][3];
    __shared__ float sw_[GPTS][3];
    int p0 = blockIdx.x * GPTS;
    int t = threadIdx.x;
    if (t < GPTS * 3) {
        int j = t / 3, k = t - j * 3;
        int p = p0 + j;
        si[j][k]  = (p >> 13) * SS + g_kidx[p * 3 + k];   // global Y row
        sw_[j][k] = g_kw[p * 3 + k];
    }
    __syncthreads();

    int c0 = t * 2;                    // 0..510
    float bb0 = b1[c0], bb1 = b1[c0 + 1];
    float s0 = 0.f, s1 = 0.f, q0 = 0.f, q1 = 0.f;

#pragma unroll 4
    for (int j = 0; j < GPTS; j++) {
        float v0 = bb0, v1 = bb1;
#pragma unroll
        for (int k = 0; k < 3; k++) {
            __half2 y = *(const __half2*)(g_Yh + (size_t)si[j][k] * MCH + c0);
            float2 yf = __half22float2(y);
            float w = sw_[j][k];
            v0 += w * yf.x; v1 += w * yf.y;
        }
        *(__half2*)&g_x1[(size_t)(p0 + j) * MCH + c0] = __floats2half2_rn(v0, v1);
        s0 += v0; q0 += v0 * v0;
        s1 += v1; q1 += v1 * v1;
    }
    atomicAdd(&g_stats[c0],           s0);
    atomicAdd(&g_stats[c0 + 1],       s1);
    atomicAdd(&g_stats[MCH + c0],     q0);
    atomicAdd(&g_stats[MCH + c0 + 1], q1);
}

// ---------------- map2: relu(bn1(x1)) -> fp16 A2; affine computed per-thread ----------------
// Block = 32-row strip; thread t owns columns (2t, 2t+1).
__global__ void __launch_bounds__(256, 4)
map2_kernel(const float* __restrict__ gamma, const float* __restrict__ beta) {
    int t = threadIdx.x;
    int c0 = t * 2;
    // per-thread BN1 affine from raw stats (L2-cached broadcast reads)
    float m0 = g_stats[c0]     * (1.0f / RR);
    float m1 = g_stats[c0 + 1] * (1.0f / RR);
    float v0 = g_stats[MCH + c0]     * (1.0f / RR) - m0 * m0;
    float v1 = g_stats[MCH + c0 + 1] * (1.0f / RR) - m1 * m1;
    float sc0 = gamma[c0]     * rsqrtf(v0 + 1e-5f);
    float sc1 = gamma[c0 + 1] * rsqrtf(v1 + 1e-5f);
    float sh0 = beta[c0]     - m0 * sc0;
    float sh1 = beta[c0 + 1] - m1 * sc1;

    size_t base = (size_t)blockIdx.x * 32 * MCH + c0;
#pragma unroll 4
    for (int r = 0; r < 32; r++) {
        __half2 h = *(const __half2*)(g_x1 + base + (size_t)r * MCH);
        float2 f = __half22float2(h);
        float a0 = fmaxf(fmaf(f.x, sc0, sh0), 0.f);
        float a1 = fmaxf(fmaf(f.y, sc1, sh1), 0.f);
        *(__half2*)(g_A2 + base + (size_t)r * MCH) = __floats2half2_rn(a0, a1);
    }
}

// ---------------- finalmap: out = relu(bn2(x2)); affine computed per-thread ----------------
__global__ void __launch_bounds__(256, 4)
finalmap_kernel(float* __restrict__ out,
                const float* __restrict__ gamma, const float* __restrict__ beta) {
    int t = threadIdx.x;
    int c0 = t * 2;
    float m0 = g_stats[2 * MCH + c0]     * (1.0f / RR);
    float m1 = g_stats[2 * MCH + c0 + 1] * (1.0f / RR);
    float v0 = g_stats[3 * MCH + c0]     * (1.0f / RR) - m0 * m0;
    float v1 = g_stats[3 * MCH + c0 + 1] * (1.0f / RR) - m1 * m1;
    float sc0 = gamma[c0]     * rsqrtf(v0 + 1e-5f);
    float sc1 = gamma[c0 + 1] * rsqrtf(v1 + 1e-5f);
    float sh0 = beta[c0]     - m0 * sc0;
    float sh1 = beta[c0 + 1] - m1 * sc1;

    size_t base = (size_t)blockIdx.x * 32 * MCH + c0;
#pragma unroll 4
    for (int r = 0; r < 32; r++) {
        __half2 h = *(const __half2*)(g_x2 + base + (size_t)r * MCH);
        float2 f = __half22float2(h);
        float2 o;
        o.x = fmaxf(fmaf(f.x, sc0, sh0), 0.f);
        o.y = fmaxf(fmaf(f.y, sc1, sh1), 0.f);
        *(float2*)(out + base + (size_t)r * MCH) = o;
    }
}

// ---------------- launch ----------------
extern "C" void kernel_launch(void* const* d_in, const int* in_sizes, int n_in,
                              void* d_out, int out_size) {
    const float* xyz     = (const float*)d_in[0];
    const float* centers = (const float*)d_in[1];
    const float* H4      = (const float*)d_in[2];
    const float* H8      = (const float*)d_in[3];
    const float* H12     = (const float*)d_in[4];
    const float* W1      = (const float*)d_in[5];
    const float* b1      = (const float*)d_in[6];
    const float* g1      = (const float*)d_in[7];
    const float* beta1   = (const float*)d_in[8];
    const float* W2      = (const float*)d_in[9];
    const float* b2      = (const float*)d_in[10];
    const float* g2      = (const float*)d_in[11];
    const float* beta2   = (const float*)d_in[12];
    float* out = (float*)d_out;

    const int SMEM_Y  = 2 * (64 + 128) * ROWSTRIDE;    // 30720
    const int SMEM_G2 = 2 * (128 + 128) * ROWSTRIDE;   // 40960
    cudaFuncSetAttribute(hmma_gemm_kernel<2, CCH, 0>,
                         cudaFuncAttributeMaxDynamicSharedMemorySize, SMEM_Y);
    cudaFuncSetAttribute(hmma_gemm_kernel<4, MCH, 1>,
                         cudaFuncAttributeMaxDynamicSharedMemorySize, SMEM_G2);

    prep_kernel<<<(W1N + W2N + FN) / 1024, 256>>>(W1, W2, H4, H8, H12);
    knn_kernel<<<RR / 256, 256>>>(xyz, centers);

    // Y = F @ W1 (2048 x 512, K=1536) — single wave (128 CTAs), fp16 out
    dim3 gy(MCH / 128, SR / 64);       // (4, 32)
    hmma_gemm_kernel<2, CCH, 0><<<gy, 256, SMEM_Y>>>(nullptr);

    // x1 = interp(Yh) + b1  (+ stats)
    gather_kernel<<<RR / GPTS, 256>>>(b1);

    // A2 = relu(bn1(x1)) — affine computed inline from stats
    map2_kernel<<<RR / 32, 256>>>(g1, beta1);

    // x2 = A2 @ W2 + b2  (+ stats)
    dim3 g2d(MCH / 128, RR / 128);     // (4, 256)
    hmma_gemm_kernel<4, MCH, 1><<<g2d, 256, SMEM_G2>>>(b2);

    // out = relu(bn2(x2)) — affine computed inline from stats
    finalmap_kernel<<<RR / 32, 256>>>(out, g2, beta2);
}